// round 16
// baseline (speedup 1.0000x reference)
#include <cuda_runtime.h>
#include <cuda_bf16.h>
#include <cstdint>

#define NPTS 8192
#define NCOLS 10
#define DIMV 3
#define NUM_CLASSES 5
#define NGROUP 10
#define EPS2 225.0f
#define MIN_POINTS 5
#define BIGC (1 << 30)

#define GCAP 1024
#define GW   32
#define GWP  33
#define MW   (NPTS / 32)
#define ROWS_PER_WARP 4
#define ROWS_PER_BLK 32
#define BLKS_PER_GRP (GCAP / ROWS_PER_BLK)

#define BARX() asm volatile("bar.sync 1, 256;" ::: "memory")

__device__ unsigned char g_grp[NPTS];
__device__ unsigned g_mmask[NGROUP][MW];
__device__ int      g_wpref[NGROUP][MW];
__device__ int      g_size[NGROUP];
__device__ int      g_list[NGROUP][GCAP];
__device__ float4   g_gpts[NGROUP][GCAP];
__device__ unsigned g_gadj[NGROUP][GCAP][GW];
__device__ unsigned g_cmask[NGROUP][GW];
__device__ unsigned g_arrive = 0;

__device__ __forceinline__ float fm(float a, float b) { return __fmul_rn(a, b); }
__device__ __forceinline__ float fa(float a, float b) { return __fadd_rn(a, b); }
__device__ __forceinline__ float fs(float a, float b) { return __fsub_rn(a, b); }

// ---- K1: group ids + membership masks + (last block) prefix scan ----
__global__ void k_prep(const float* __restrict__ x) {
    int tid = threadIdx.x;                   // 512 threads, grid 16
    int i = blockIdx.x * 512 + tid;
    const float* xr = x + i * NCOLS;
    int b = (int)xr[3];
    float best = xr[5];
    int cls = 0;
#pragma unroll
    for (int k = 1; k < NUM_CLASSES; k++) {
        float v = xr[5 + k];
        if (v > best) { best = v; cls = k; }
    }
    int g = b * NUM_CLASSES + cls;
    g_grp[i] = (unsigned char)g;
    int lane = tid & 31;
    int word = i >> 5;
#pragma unroll
    for (int g2 = 0; g2 < NGROUP; g2++) {
        unsigned m = __ballot_sync(0xffffffffu, g == g2);
        if (lane == g2) g_mmask[g2][word] = m;
    }
    __threadfence();

    __shared__ int s_last;
    if (tid == 0) s_last = (atomicAdd(&g_arrive, 1u) == 15u);
    __syncthreads();
    if (!s_last) return;

    if (tid == 0) g_arrive = 0;
    if (tid < NGROUP * GW) ((unsigned*)g_cmask)[tid] = 0;
    int warp = tid >> 5;
    if (warp >= NGROUP) return;
    int run = 0;
#pragma unroll
    for (int c = 0; c < MW / 32; c++) {
        int v = __popc(g_mmask[warp][c * 32 + lane]);
        int s = v;
#pragma unroll
        for (int o = 1; o < 32; o <<= 1) {
            int t = __shfl_up_sync(0xffffffffu, s, o);
            if (lane >= o) s += t;
        }
        g_wpref[warp][c * 32 + lane] = run + s - v;
        run += __shfl_sync(0xffffffffu, s, 31);
    }
    if (lane == 0) g_size[warp] = run;
}

// ---- K2: scatter points into group arrays ----
__global__ void k_scatter(const float* __restrict__ x) {
    int i = blockIdx.x * 256 + threadIdx.x;
    int g = g_grp[i];
    int w = i >> 5, b = i & 31;
    int loc = g_wpref[g][w] + __popc(g_mmask[g][w] & ((1u << b) - 1u));
    if (loc >= GCAP) return;
    const float* xr = x + i * NCOLS;
    float cx = xr[0], cy = xr[1], cz = xr[2];
    float p2 = fa(fa(fm(cx, cx), fm(cy, cy)), fm(cz, cz));
    g_list[g][loc] = i;
    g_gpts[g][loc] = make_float4(cx, cy, cz, p2);
}

// ---- K3: adjacency bitmap + core bits, 4 rows per warp (round-6 verbatim) ----
__global__ void k_adj() {
    __shared__ float4 sp[GCAP];
    int g  = blockIdx.x / BLKS_PER_GRP;
    int rb = blockIdx.x % BLKS_PER_GRP;
    int G  = g_size[g];
    int rowbase = rb * ROWS_PER_BLK;
    if (rowbase >= G) return;
    for (int j = threadIdx.x; j < G; j += 256) sp[j] = g_gpts[g][j];
    __syncthreads();

    int warp = threadIdx.x >> 5, lane = threadIdx.x & 31;
    int r0 = rowbase + warp * ROWS_PER_WARP;
    if (r0 >= G) return;
    float4 p0 = sp[min(r0 + 0, G - 1)];
    float4 p1 = sp[min(r0 + 1, G - 1)];
    float4 p2 = sp[min(r0 + 2, G - 1)];
    float4 p3 = sp[min(r0 + 3, G - 1)];
    int nw = (G + 31) >> 5;
    int d0 = 0, d1 = 0, d2c = 0, d3 = 0;
    for (int w = 0; w < nw; w++) {
        int j = w * 32 + lane;
        float4 pj = (j < G) ? sp[j] : make_float4(1e18f, 1e18f, 1e18f, 1e36f);
#define D2(P) fs(fa((P).w, pj.w), fm(2.0f, fa(fa(fm((P).x, pj.x), fm((P).y, pj.y)), fm((P).z, pj.z))))
        unsigned m0 = __ballot_sync(0xffffffffu, D2(p0) < EPS2);
        unsigned m1 = __ballot_sync(0xffffffffu, D2(p1) < EPS2);
        unsigned m2 = __ballot_sync(0xffffffffu, D2(p2) < EPS2);
        unsigned m3 = __ballot_sync(0xffffffffu, D2(p3) < EPS2);
#undef D2
        if (lane == 0) {
            g_gadj[g][r0][w] = m0;
            if (r0 + 1 < G) g_gadj[g][r0 + 1][w] = m1;
            if (r0 + 2 < G) g_gadj[g][r0 + 2][w] = m2;
            if (r0 + 3 < G) g_gadj[g][r0 + 3][w] = m3;
        }
        d0 += __popc(m0); d1 += __popc(m1); d2c += __popc(m2); d3 += __popc(m3);
    }
    if (lane < ROWS_PER_WARP) {
        int row = r0 + lane;
        int deg = (lane == 0) ? d0 : (lane == 1) ? d1 : (lane == 2) ? d2c : d3;
        if (row < G && deg >= MIN_POINTS)
            atomicOr(&g_cmask[g][row >> 5], 1u << (row & 31));
    }
}

// ---- K4: cc with warp-specialized BFS (8 warps, named barrier) ----
extern __shared__ unsigned s_dyn[];
__global__ void __launch_bounds__(1024, 1)
k_cc(const float* __restrict__ x, float* __restrict__ out) {
    unsigned* sadj = s_dyn;                       // GCAP * GWP words (132 KB)
    __shared__ unsigned cmask[GW];
    __shared__ unsigned visited[GW];
    __shared__ unsigned frontier[GW];
    __shared__ unsigned warpacc[8][GWP];
    __shared__ int      scid[GCAP];
    __shared__ int      s_seed, s_any, s_cluster;

    int g    = blockIdx.x;
    int tid  = threadIdx.x;
    int warp = tid >> 5, lane = tid & 31;
    int G    = g_size[g];
    int nw   = (G + 31) >> 5;

    // stage adjacency (uint4 global loads -> padded smem rows), all 1024 threads
    for (int t = tid; t < G * 8; t += 1024) {
        int r = t >> 3, q = t & 7;
        uint4 v = ((const uint4*)g_gadj[g][r])[q];
        unsigned* dst = sadj + r * GWP + q * 4;
        dst[0] = v.x; dst[1] = v.y; dst[2] = v.z; dst[3] = v.w;
    }
    for (int i = tid; i < GCAP; i += 1024) scid[i] = BIGC;
    if (tid < GW) {
        cmask[tid]   = g_cmask[g][tid];
        visited[tid] = 0;
        frontier[tid] = 0;
    }
    if (tid == 0) s_cluster = 0;
    __syncthreads();

    // ---- BFS: warps 0-7 only; named barrier bar.sync(1,256) ----
    if (warp < 8) {
        for (;;) {
            if (warp == 0) {
                unsigned avail = cmask[lane] & ~visited[lane];
                unsigned bal = __ballot_sync(0xffffffffu, avail != 0);
                if (lane == 0) s_seed = -1;
                if (bal) {
                    int wsel = __ffs(bal) - 1;
                    unsigned aw = __shfl_sync(0xffffffffu, avail, wsel);
                    if (lane == 0) s_seed = wsel * 32 + (__ffs(aw) - 1);
                }
            }
            BARX();
            int seed = s_seed;
            if (seed < 0) break;
            int cluster = s_cluster;
            if (tid < GW) frontier[tid] = (tid == (seed >> 5)) ? (1u << (seed & 31)) : 0;
            if (tid == 0) {
                visited[seed >> 5] |= (1u << (seed & 31));
                scid[seed] = cluster;
            }
            BARX();

            for (;;) {
                // expansion: warp w owns frontier words w, w+8, w+16, w+24
                unsigned acc = 0;
#pragma unroll
                for (int k = 0; k < 4; k++) {
                    int w8 = warp + k * 8;
                    unsigned f = frontier[w8];
                    int rbase = w8 * 32;
                    while (f) {
                        int b = __ffs(f) - 1;
                        f &= f - 1;
                        acc |= sadj[(rbase + b) * GWP + lane];
                    }
                }
                warpacc[warp][lane] = acc;
                BARX();
                // consolidation: warp0, 8 ORs per lane
                if (warp == 0) {
                    unsigned n = 0;
#pragma unroll
                    for (int w2 = 0; w2 < 8; w2++) n |= warpacc[w2][lane];
                    n &= cmask[lane] & ~visited[lane];
                    frontier[lane] = n;
                    visited[lane] |= n;
                    unsigned anyb = __ballot_sync(0xffffffffu, n != 0);
                    if (lane == 0) s_any = (anyb != 0);
                }
                BARX();
                // scid write: 256 threads cover 1024 points
#pragma unroll
                for (int k = 0; k < 4; k++) {
                    int p = tid + k * 256;
                    if ((frontier[p >> 5] >> (p & 31)) & 1) scid[p] = cluster;
                }
                if (!s_any) break;
            }
            if (tid == 0) s_cluster = cluster + 1;
        }
    }
    __syncthreads();

    // border labels + output (all 1024 threads)
    for (int i = tid; i < G; i += 1024) {
        int label;
        int own = scid[i];
        if (own < BIGC) {
            label = own;
        } else {
            int m = BIGC;
            const unsigned* arow = sadj + i * GWP;
            for (int w = 0; w < nw; w++) {
                unsigned a = arow[w] & cmask[w];
                while (a) {
                    int b = __ffs(a) - 1;
                    a &= a - 1;
                    m = min(m, scid[w * 32 + b]);
                }
            }
            label = (m < BIGC) ? m : -1;
        }
        int gi = g_list[g][i];
        out[gi] = (float)label;
        const float* xr = x + gi * NCOLS;
        float* cr = out + NPTS + gi * (DIMV + 2);
        if (label >= 0) {
#pragma unroll
            for (int k = 0; k < 5; k++) cr[k] = xr[k];
        } else {
#pragma unroll
            for (int k = 0; k < 5; k++) cr[k] = 0.0f;
        }
    }
}

extern "C" void kernel_launch(void* const* d_in, const int* in_sizes, int n_in,
                              void* d_out, int out_size) {
    const float* x = (const float*)d_in[0];
    float* out = (float*)d_out;
    (void)in_sizes; (void)n_in; (void)out_size;

    static int smem_set = 0;
    const int cc_smem = GCAP * GWP * (int)sizeof(unsigned);  // 132 KB
    if (!smem_set) {
        cudaFuncSetAttribute(k_cc, cudaFuncAttributeMaxDynamicSharedMemorySize, cc_smem);
        smem_set = 1;
    }

    k_prep<<<16, 512>>>(x);
    k_scatter<<<NPTS / 256, 256>>>(x);
    k_adj<<<NGROUP * BLKS_PER_GRP, 256>>>();
    k_cc<<<NGROUP, 1024, cc_smem>>>(x, out);
}

// round 17
// speedup vs baseline: 1.1750x; 1.1750x over previous
#include <cuda_runtime.h>
#include <cuda_bf16.h>
#include <cstdint>

#define NPTS 8192
#define NCOLS 10
#define DIMV 3
#define NUM_CLASSES 5
#define NGROUP 10
#define EPS2 225.0f
#define MIN_POINTS 5
#define BIGC (1 << 30)

#define GCAP 1024
#define GW   32
#define GWP  33
#define MW   (NPTS / 32)
#define ROWS_PER_WARP 4
#define ROWS_PER_BLK 32
#define BLKS_PER_GRP (GCAP / ROWS_PER_BLK)

typedef unsigned long long u64;

__device__ unsigned char g_grp[NPTS];
__device__ unsigned g_mmask[NGROUP][MW];
__device__ int      g_wpref[NGROUP][MW];
__device__ int      g_size[NGROUP];
__device__ int      g_list[NGROUP][GCAP];
__device__ float4   g_gpts[NGROUP][GCAP];
__device__ unsigned g_gadj[NGROUP][GCAP][GW];
__device__ unsigned g_cmask[NGROUP][GW];
__device__ unsigned g_arrive = 0;

__device__ __forceinline__ float fm(float a, float b) { return __fmul_rn(a, b); }
__device__ __forceinline__ float fa(float a, float b) { return __fadd_rn(a, b); }

__device__ __forceinline__ u64 pk(float a, float b) {
    u64 r; asm("mov.b64 %0, {%1, %2};" : "=l"(r) : "f"(a), "f"(b)); return r;
}
__device__ __forceinline__ void unpk(u64 p, float& lo, float& hi) {
    asm("mov.b64 {%0, %1}, %2;" : "=f"(lo), "=f"(hi) : "l"(p));
}
__device__ __forceinline__ u64 mul2(u64 a, u64 b) {
    u64 r; asm("mul.rn.f32x2 %0, %1, %2;" : "=l"(r) : "l"(a), "l"(b)); return r;
}
__device__ __forceinline__ u64 add2(u64 a, u64 b) {
    u64 r; asm("add.rn.f32x2 %0, %1, %2;" : "=l"(r) : "l"(a), "l"(b)); return r;
}

// ---- K1: group ids + membership masks + (last block) prefix scan ----
__global__ void k_prep(const float* __restrict__ x) {
    int tid = threadIdx.x;                   // 512 threads, grid 16
    int i = blockIdx.x * 512 + tid;
    const float* xr = x + i * NCOLS;
    int b = (int)xr[3];
    float best = xr[5];
    int cls = 0;
#pragma unroll
    for (int k = 1; k < NUM_CLASSES; k++) {
        float v = xr[5 + k];
        if (v > best) { best = v; cls = k; }
    }
    int g = b * NUM_CLASSES + cls;
    g_grp[i] = (unsigned char)g;
    int lane = tid & 31;
    int word = i >> 5;
#pragma unroll
    for (int g2 = 0; g2 < NGROUP; g2++) {
        unsigned m = __ballot_sync(0xffffffffu, g == g2);
        if (lane == g2) g_mmask[g2][word] = m;
    }
    __threadfence();

    __shared__ int s_last;
    if (tid == 0) s_last = (atomicAdd(&g_arrive, 1u) == 15u);
    __syncthreads();
    if (!s_last) return;

    if (tid == 0) g_arrive = 0;
    if (tid < NGROUP * GW) ((unsigned*)g_cmask)[tid] = 0;
    int warp = tid >> 5;
    if (warp >= NGROUP) return;
    int run = 0;
#pragma unroll
    for (int c = 0; c < MW / 32; c++) {
        int v = __popc(g_mmask[warp][c * 32 + lane]);
        int s = v;
#pragma unroll
        for (int o = 1; o < 32; o <<= 1) {
            int t = __shfl_up_sync(0xffffffffu, s, o);
            if (lane >= o) s += t;
        }
        g_wpref[warp][c * 32 + lane] = run + s - v;
        run += __shfl_sync(0xffffffffu, s, 31);
    }
    if (lane == 0) g_size[warp] = run;
}

// ---- K2: scatter points into group arrays ----
__global__ void k_scatter(const float* __restrict__ x) {
    int i = blockIdx.x * 256 + threadIdx.x;
    int g = g_grp[i];
    int w = i >> 5, b = i & 31;
    int loc = g_wpref[g][w] + __popc(g_mmask[g][w] & ((1u << b) - 1u));
    if (loc >= GCAP) return;
    const float* xr = x + i * NCOLS;
    float cx = xr[0], cy = xr[1], cz = xr[2];
    float p2 = fa(fa(fm(cx, cx), fm(cy, cy)), fm(cz, cz));
    g_list[g][loc] = i;
    g_gpts[g][loc] = make_float4(cx, cy, cz, p2);
}

// ---- K3: adjacency via packed f32x2 (2 columns per lane-op), 4 rows/warp ----
__global__ void k_adj() {
    __shared__ float4 sp[GCAP];
    int g  = blockIdx.x / BLKS_PER_GRP;
    int rb = blockIdx.x % BLKS_PER_GRP;
    int G  = g_size[g];
    int rowbase = rb * ROWS_PER_BLK;
    if (rowbase >= G) return;
    int Gpad = (G + 63) & ~63;
    for (int j = threadIdx.x; j < G; j += 256) sp[j] = g_gpts[g][j];
    for (int j = G + threadIdx.x; j < Gpad; j += 256)
        sp[j] = make_float4(1e18f, 1e18f, 1e18f, 1e36f);   // pred false, no NaN
    __syncthreads();

    int warp = threadIdx.x >> 5, lane = threadIdx.x & 31;
    int r0 = rowbase + warp * ROWS_PER_WARP;
    if (r0 >= G) return;
    float4 p0 = sp[min(r0 + 0, G - 1)];
    float4 p1 = sp[min(r0 + 1, G - 1)];
    float4 p2 = sp[min(r0 + 2, G - 1)];
    float4 p3 = sp[min(r0 + 3, G - 1)];
    u64 p0x = pk(p0.x, p0.x), p0y = pk(p0.y, p0.y), p0z = pk(p0.z, p0.z), p0w = pk(p0.w, p0.w);
    u64 p1x = pk(p1.x, p1.x), p1y = pk(p1.y, p1.y), p1z = pk(p1.z, p1.z), p1w = pk(p1.w, p1.w);
    u64 p2x = pk(p2.x, p2.x), p2y = pk(p2.y, p2.y), p2z = pk(p2.z, p2.z), p2w = pk(p2.w, p2.w);
    u64 p3x = pk(p3.x, p3.x), p3y = pk(p3.y, p3.y), p3z = pk(p3.z, p3.z), p3w = pk(p3.w, p3.w);
    const u64 cneg2 = pk(-2.0f, -2.0f);

    int nwp = Gpad >> 6;
    int d0 = 0, d1 = 0, d2c = 0, d3 = 0;
    for (int wp = 0; wp < nwp; wp++) {
        float4 a = sp[wp * 64 + lane];
        float4 b2 = sp[wp * 64 + 32 + lane];
        u64 qx = pk(a.x, b2.x), qy = pk(a.y, b2.y), qz = pk(a.z, b2.z), qw = pk(a.w, b2.w);
        // d2 = (pi.w + pj.w) + (-2)*dot  — bit-identical to fs(fa(.,.), fm(2,dot))
#define ROWD2(PX, PY, PZ, PW, MA, MB) {                                         \
        u64 dot = add2(add2(mul2(PX, qx), mul2(PY, qy)), mul2(PZ, qz));         \
        u64 dd  = add2(add2(PW, qw), mul2(cneg2, dot));                         \
        float lo, hi; unpk(dd, lo, hi);                                         \
        MA = __ballot_sync(0xffffffffu, lo < EPS2);                             \
        MB = __ballot_sync(0xffffffffu, hi < EPS2); }
        unsigned m0A, m0B, m1A, m1B, m2A, m2B, m3A, m3B;
        ROWD2(p0x, p0y, p0z, p0w, m0A, m0B);
        ROWD2(p1x, p1y, p1z, p1w, m1A, m1B);
        ROWD2(p2x, p2y, p2z, p2w, m2A, m2B);
        ROWD2(p3x, p3y, p3z, p3w, m3A, m3B);
#undef ROWD2
        if (lane == 0) {
            int wA = wp * 2, wB = wA + 1;
            g_gadj[g][r0][wA] = m0A; g_gadj[g][r0][wB] = m0B;
            if (r0 + 1 < G) { g_gadj[g][r0 + 1][wA] = m1A; g_gadj[g][r0 + 1][wB] = m1B; }
            if (r0 + 2 < G) { g_gadj[g][r0 + 2][wA] = m2A; g_gadj[g][r0 + 2][wB] = m2B; }
            if (r0 + 3 < G) { g_gadj[g][r0 + 3][wA] = m3A; g_gadj[g][r0 + 3][wB] = m3B; }
        }
        d0 += __popc(m0A) + __popc(m0B);
        d1 += __popc(m1A) + __popc(m1B);
        d2c += __popc(m2A) + __popc(m2B);
        d3 += __popc(m3A) + __popc(m3B);
    }
    if (lane < ROWS_PER_WARP) {
        int row = r0 + lane;
        int deg = (lane == 0) ? d0 : (lane == 1) ? d1 : (lane == 2) ? d2c : d3;
        if (row < G && deg >= MIN_POINTS)
            atomicOr(&g_cmask[g][row >> 5], 1u << (row & 31));
    }
}

// ---- K4: per-group bitset-BFS CC + border labels + output (round-6 body) ----
extern __shared__ unsigned s_dyn[];
__global__ void k_cc(const float* __restrict__ x, float* __restrict__ out) {
    unsigned* sadj = s_dyn;                       // GCAP * GWP words
    __shared__ unsigned cmask[GW];
    __shared__ unsigned visited[GW];
    __shared__ unsigned frontier[GW];
    __shared__ unsigned warpacc[32][GWP];
    __shared__ int      scid[GCAP];
    __shared__ int      s_seed, s_any, s_cluster;

    int g    = blockIdx.x;
    int tid  = threadIdx.x;
    int warp = tid >> 5, lane = tid & 31;
    int G    = g_size[g];
    int nw   = (G + 31) >> 5;

    if (tid < GW) {
        cmask[tid]   = g_cmask[g][tid];
        visited[tid] = 0;
    }
    // uint4 staging (4x fewer global loads than scalar)
    for (int t = tid; t < G * 8; t += 1024) {
        int r = t >> 3, q = t & 7;
        uint4 v = ((const uint4*)g_gadj[g][r])[q];
        unsigned* dst = sadj + r * GWP + q * 4;
        dst[0] = v.x; dst[1] = v.y; dst[2] = v.z; dst[3] = v.w;
    }
    for (int i = tid; i < GCAP; i += 1024) scid[i] = BIGC;
    if (tid == 0) s_cluster = 0;
    __syncthreads();

    // flood fill, seeding at the smallest unvisited core each time
    for (;;) {
        if (warp == 0) {
            unsigned avail = cmask[lane] & ~visited[lane];
            unsigned bal = __ballot_sync(0xffffffffu, avail != 0);
            if (lane == 0) s_seed = -1;
            if (bal) {
                int wsel = __ffs(bal) - 1;
                unsigned aw = __shfl_sync(0xffffffffu, avail, wsel);
                if (lane == 0) s_seed = wsel * 32 + (__ffs(aw) - 1);
            }
        }
        __syncthreads();
        int seed = s_seed;
        if (seed < 0) break;
        int cluster = s_cluster;
        if (tid < GW) frontier[tid] = (tid == (seed >> 5)) ? (1u << (seed & 31)) : 0;
        if (tid == 0) {
            visited[seed >> 5] |= (1u << (seed & 31));
            scid[seed] = cluster;
        }
        __syncthreads();

        for (;;) {
            unsigned f = frontier[warp];
            unsigned acc = 0;
            while (f) {
                int b = __ffs(f) - 1;
                f &= f - 1;
                acc |= sadj[(warp * 32 + b) * GWP + lane];
            }
            warpacc[warp][lane] = acc;
            __syncthreads();
            if (warp == 0) {
                unsigned n = 0;
#pragma unroll
                for (int w2 = 0; w2 < 32; w2++) n |= warpacc[w2][lane];
                n &= cmask[lane] & ~visited[lane];
                frontier[lane] = n;
                visited[lane] |= n;
                unsigned anyb = __ballot_sync(0xffffffffu, n != 0);
                if (lane == 0) s_any = (anyb != 0);
            }
            __syncthreads();
            if ((frontier[warp] >> lane) & 1) scid[warp * 32 + lane] = cluster;
            if (!s_any) break;
        }
        if (tid == 0) s_cluster = cluster + 1;
    }
    __syncthreads();

    // border labels + output
    for (int i = tid; i < G; i += 1024) {
        int label;
        int own = scid[i];
        if (own < BIGC) {
            label = own;
        } else {
            int m = BIGC;
            const unsigned* arow = sadj + i * GWP;
            for (int w = 0; w < nw; w++) {
                unsigned a = arow[w] & cmask[w];
                while (a) {
                    int b = __ffs(a) - 1;
                    a &= a - 1;
                    m = min(m, scid[w * 32 + b]);
                }
            }
            label = (m < BIGC) ? m : -1;
        }
        int gi = g_list[g][i];
        out[gi] = (float)label;
        const float* xr = x + gi * NCOLS;
        float* cr = out + NPTS + gi * (DIMV + 2);
        if (label >= 0) {
#pragma unroll
            for (int k = 0; k < 5; k++) cr[k] = xr[k];
        } else {
#pragma unroll
            for (int k = 0; k < 5; k++) cr[k] = 0.0f;
        }
    }
}

extern "C" void kernel_launch(void* const* d_in, const int* in_sizes, int n_in,
                              void* d_out, int out_size) {
    const float* x = (const float*)d_in[0];
    float* out = (float*)d_out;
    (void)in_sizes; (void)n_in; (void)out_size;

    static int smem_set = 0;
    const int cc_smem = GCAP * GWP * (int)sizeof(unsigned);  // 132 KB
    if (!smem_set) {
        cudaFuncSetAttribute(k_cc, cudaFuncAttributeMaxDynamicSharedMemorySize, cc_smem);
        smem_set = 1;
    }

    k_prep<<<16, 512>>>(x);
    k_scatter<<<NPTS / 256, 256>>>(x);
    k_adj<<<NGROUP * BLKS_PER_GRP, 256>>>();
    k_cc<<<NGROUP, 1024, cc_smem>>>(x, out);
}